// round 1
// baseline (speedup 1.0000x reference)
#include <cuda_runtime.h>
#include <cuda_bf16.h>

// Problem constants
#define S_LEN 4096
#define D_MODEL 512
#define N_HEADS 8
#define HD 64          // head dim
#define KV_W 1024      // 2*D

// ---------------- scratch (static device memory; no allocs) ----------------
__device__ float g_q[S_LEN * D_MODEL];     // 8 MB
__device__ float g_kv[S_LEN * KV_W];       // 16 MB (K | V)
__device__ float g_att[S_LEN * D_MODEL];   // 8 MB

// ---------------- SGEMM: C[M,N] = A[M,K] @ B[K,N] + bias[N] ----------------
// 128x128 block tile, BK=8, 256 threads, 8x8 per-thread fragment.
// M,N,K all multiples of the tile sizes for this problem -> no bounds checks.
#define GBM 128
#define GBN 128
#define GBK 8

__global__ __launch_bounds__(256) void sgemm_bias(
    const float* __restrict__ A, const float* __restrict__ B,
    const float* __restrict__ bias, float* __restrict__ C,
    int M, int N, int K)
{
    __shared__ float Ast[GBK][GBM];   // A tile, transposed
    __shared__ float Bs[GBK][GBN];

    const int tid = threadIdx.x;
    const int tx = tid & 15;          // 0..15
    const int ty = tid >> 4;          // 0..15
    const int row0 = blockIdx.y * GBM;
    const int col0 = blockIdx.x * GBN;

    // load mapping
    const int arow = tid >> 1;              // 0..127
    const int acol = (tid & 1) * 4;         // 0 or 4
    const int brow = tid >> 5;              // 0..7
    const int bcol = (tid & 31) * 4;        // 0..124

    float acc[8][8];
#pragma unroll
    for (int i = 0; i < 8; i++)
#pragma unroll
        for (int j = 0; j < 8; j++) acc[i][j] = 0.f;

    for (int k0 = 0; k0 < K; k0 += GBK) {
        float4 av = *reinterpret_cast<const float4*>(&A[(size_t)(row0 + arow) * K + k0 + acol]);
        float4 bv = *reinterpret_cast<const float4*>(&B[(size_t)(k0 + brow) * N + col0 + bcol]);
        Ast[acol + 0][arow] = av.x;
        Ast[acol + 1][arow] = av.y;
        Ast[acol + 2][arow] = av.z;
        Ast[acol + 3][arow] = av.w;
        *reinterpret_cast<float4*>(&Bs[brow][bcol]) = bv;
        __syncthreads();

#pragma unroll
        for (int kk = 0; kk < GBK; kk++) {
            float a[8], b[8];
#pragma unroll
            for (int i = 0; i < 8; i++) a[i] = Ast[kk][ty * 8 + i];
#pragma unroll
            for (int j = 0; j < 8; j++) b[j] = Bs[kk][tx * 8 + j];
#pragma unroll
            for (int i = 0; i < 8; i++)
#pragma unroll
                for (int j = 0; j < 8; j++) acc[i][j] += a[i] * b[j];
        }
        __syncthreads();
    }

#pragma unroll
    for (int i = 0; i < 8; i++) {
        const int r = row0 + ty * 8 + i;
#pragma unroll
        for (int j = 0; j < 8; j++) {
            const int c = col0 + tx * 8 + j;
            C[(size_t)r * N + c] = acc[i][j] + bias[c];
        }
    }
}

// ---------------- causal flash attention (fp32) ----------------
// grid: (S/64 query blocks, H heads), 256 threads.
// Per block: Q tile [64,64] resident; loop key blocks kb=0..qb.
// Each thread owns a 4x4 fragment: rows ty*4+i (queries), cols tx*4+j
// (keys for S/P, head-dims for O). Online softmax with shfl_xor row
// reductions (width 16 = the tx group). K and V share one smem buffer.
#define FPITCH 65   // pad: kills the 16-way bank conflict on K[key][dim] reads

__global__ __launch_bounds__(256) void flash_attn(
    const float* __restrict__ Q, const float* __restrict__ KV,
    float* __restrict__ O)
{
    extern __shared__ float sm[];
    float* Qs = sm;                       // [64][FPITCH]
    float* Ks = sm + 64 * FPITCH;         // K tile, then reused as V tile
    float* Ps = sm + 2 * 64 * FPITCH;     // exp'd scores

    const int qb = gridDim.x - 1 - blockIdx.x;  // heavy blocks first
    const int h  = blockIdx.y;
    const int tid = threadIdx.x;
    const int tx = tid & 15;
    const int ty = tid >> 4;
    const int q0 = qb * 64;

    // load Q tile (pre-scaled by 1/sqrt(HD))
    for (int e = tid; e < 64 * 64; e += 256) {
        const int r = e >> 6, c = e & 63;
        Qs[r * FPITCH + c] = Q[(size_t)(q0 + r) * D_MODEL + h * HD + c] * 0.125f;
    }

    float o[4][4];
    float m_i[4], l_i[4];
#pragma unroll
    for (int i = 0; i < 4; i++) {
        m_i[i] = -1e30f; l_i[i] = 0.f;
#pragma unroll
        for (int j = 0; j < 4; j++) o[i][j] = 0.f;
    }

    for (int kb = 0; kb <= qb; kb++) {
        const int k0 = kb * 64;

        __syncthreads();   // Qs ready (iter 0) / prev V+P reads done
        // load K tile [key][dim]
        for (int e = tid; e < 64 * 64; e += 256) {
            const int r = e >> 6, c = e & 63;
            Ks[r * FPITCH + c] = KV[(size_t)(k0 + r) * KV_W + h * HD + c];
        }
        __syncthreads();

        // S = Q K^T fragment
        float s[4][4];
#pragma unroll
        for (int i = 0; i < 4; i++)
#pragma unroll
            for (int j = 0; j < 4; j++) s[i][j] = 0.f;

#pragma unroll 16
        for (int kk = 0; kk < 64; kk++) {
            float a[4], b[4];
#pragma unroll
            for (int i = 0; i < 4; i++) a[i] = Qs[(ty * 4 + i) * FPITCH + kk];
#pragma unroll
            for (int j = 0; j < 4; j++) b[j] = Ks[(tx * 4 + j) * FPITCH + kk];
#pragma unroll
            for (int i = 0; i < 4; i++)
#pragma unroll
                for (int j = 0; j < 4; j++) s[i][j] += a[i] * b[j];
        }

        // causal mask on the diagonal block
        if (kb == qb) {
#pragma unroll
            for (int i = 0; i < 4; i++)
#pragma unroll
                for (int j = 0; j < 4; j++)
                    if (tx * 4 + j > ty * 4 + i) s[i][j] = -1e30f;
        }

        __syncthreads();   // all K reads done before V overwrites the buffer
        // load V tile into Ks buffer
        for (int e = tid; e < 64 * 64; e += 256) {
            const int r = e >> 6, c = e & 63;
            Ks[r * FPITCH + c] = KV[(size_t)(k0 + r) * KV_W + D_MODEL + h * HD + c];
        }

        // online softmax (row reductions across the 16 tx threads)
#pragma unroll
        for (int i = 0; i < 4; i++) {
            float mx = s[i][0];
#pragma unroll
            for (int j = 1; j < 4; j++) mx = fmaxf(mx, s[i][j]);
#pragma unroll
            for (int off = 8; off >= 1; off >>= 1)
                mx = fmaxf(mx, __shfl_xor_sync(0xffffffffu, mx, off, 16));

            const float m_new = fmaxf(m_i[i], mx);
            const float alpha = __expf(m_i[i] - m_new);
            float rs = 0.f;
#pragma unroll
            for (int j = 0; j < 4; j++) {
                s[i][j] = __expf(s[i][j] - m_new);
                rs += s[i][j];
            }
#pragma unroll
            for (int off = 8; off >= 1; off >>= 1)
                rs += __shfl_xor_sync(0xffffffffu, rs, off, 16);

            l_i[i] = l_i[i] * alpha + rs;
            m_i[i] = m_new;
#pragma unroll
            for (int j = 0; j < 4; j++) o[i][j] *= alpha;
            // stash P tile for the PV product
#pragma unroll
            for (int j = 0; j < 4; j++)
                Ps[(ty * 4 + i) * FPITCH + tx * 4 + j] = s[i][j];
        }
        __syncthreads();   // P written, V loaded

        // O += P V  (cols of o are head dims)
#pragma unroll 16
        for (int kk = 0; kk < 64; kk++) {
            float p[4], v[4];
#pragma unroll
            for (int i = 0; i < 4; i++) p[i] = Ps[(ty * 4 + i) * FPITCH + kk];
#pragma unroll
            for (int j = 0; j < 4; j++) v[j] = Ks[kk * FPITCH + tx * 4 + j];
#pragma unroll
            for (int i = 0; i < 4; i++)
#pragma unroll
                for (int j = 0; j < 4; j++) o[i][j] += p[i] * v[j];
        }
    }

    // normalize and write [S][H][HD]
#pragma unroll
    for (int i = 0; i < 4; i++) {
        const float inv = 1.f / l_i[i];
        const int r = q0 + ty * 4 + i;
#pragma unroll
        for (int j = 0; j < 4; j++)
            O[(size_t)r * D_MODEL + h * HD + tx * 4 + j] = o[i][j] * inv;
    }
}

// ---------------- launch ----------------
extern "C" void kernel_launch(void* const* d_in, const int* in_sizes, int n_in,
                              void* d_out, int out_size)
{
    const float* query = (const float*)d_in[0];
    const float* value = (const float*)d_in[1];
    // d_in[2] is the additive mask: causal by construction -> handled structurally
    const float* wq_k  = (const float*)d_in[3];
    const float* wq_b  = (const float*)d_in[4];
    const float* wkv_k = (const float*)d_in[5];
    const float* wkv_b = (const float*)d_in[6];
    const float* wo_k  = (const float*)d_in[7];
    const float* wo_b  = (const float*)d_in[8];
    float* out = (float*)d_out;

    float *q_ptr = nullptr, *kv_ptr = nullptr, *att_ptr = nullptr;
    cudaGetSymbolAddress((void**)&q_ptr,  g_q);
    cudaGetSymbolAddress((void**)&kv_ptr, g_kv);
    cudaGetSymbolAddress((void**)&att_ptr, g_att);

    // Q projection: [4096,512] = query @ wq_k + wq_b
    sgemm_bias<<<dim3(D_MODEL / GBN, S_LEN / GBM), 256>>>(
        query, wq_k, wq_b, q_ptr, S_LEN, D_MODEL, D_MODEL);

    // KV projection: [4096,1024] = value @ wkv_k + wkv_b
    sgemm_bias<<<dim3(KV_W / GBN, S_LEN / GBM), 256>>>(
        value, wkv_k, wkv_b, kv_ptr, S_LEN, KV_W, D_MODEL);

    // causal flash attention
    const int smem = 3 * 64 * FPITCH * (int)sizeof(float);  // 49920 B
    cudaFuncSetAttribute(flash_attn, cudaFuncAttributeMaxDynamicSharedMemorySize, smem);
    flash_attn<<<dim3(S_LEN / 64, N_HEADS), 256, smem>>>(q_ptr, kv_ptr, att_ptr);

    // output projection: [4096,512] = att @ wo_k + wo_b
    sgemm_bias<<<dim3(D_MODEL / GBN, S_LEN / GBM), 256>>>(
        att_ptr, wo_k, wo_b, out, S_LEN, D_MODEL, D_MODEL);
}

// round 2
// speedup vs baseline: 1.0660x; 1.0660x over previous
#include <cuda_runtime.h>
#include <cuda_bf16.h>

// Problem constants
#define S_LEN 4096
#define D_MODEL 512
#define N_HEADS 8
#define HD 64
#define KV_W 1024

// ---------------- scratch ----------------
__device__ float g_q[S_LEN * D_MODEL];
__device__ float g_kv[S_LEN * KV_W];
__device__ float g_att[S_LEN * D_MODEL];

// ---------------- SGEMM body: BM=128, BN=64, BK=16, 256 thr, 8x4 frag ----------------
#define GBM 128
#define GBN 64
#define GBK 16
#define AP 132          // As pitch (transposed A tile [k][m])
#define BP 68           // Bs pitch ([k][n])
#define SG_SMEM (2 * (GBK * AP + GBK * BP))   // floats, double buffered

__device__ __forceinline__ void sgemm_body(
    const float* __restrict__ A, const float* __restrict__ B,
    const float* __restrict__ bias, float* __restrict__ C,
    int N, int K, int row0, int col0, float* sm)
{
    float* As0 = sm;
    float* As1 = sm + GBK * AP;
    float* Bs0 = sm + 2 * GBK * AP;
    float* Bs1 = Bs0 + GBK * BP;

    const int tid = threadIdx.x;
    const int tx = tid & 15;        // 16 col groups * 4
    const int ty = tid >> 4;        // 16 row groups * 8

    // A load: 128x16 tile = 512 float4; thread does 2 (rows ar0, ar0+64)
    const int ar0 = tid >> 2;            // 0..63
    const int ac4 = (tid & 3) * 4;       // 0,4,8,12
    // B load: 16x64 tile = 256 float4
    const int br  = tid >> 4;            // 0..15
    const int bc4 = (tid & 15) * 4;

    float4 aR0 = *reinterpret_cast<const float4*>(&A[(size_t)(row0 + ar0) * K + ac4]);
    float4 aR1 = *reinterpret_cast<const float4*>(&A[(size_t)(row0 + ar0 + 64) * K + ac4]);
    float4 bR  = *reinterpret_cast<const float4*>(&B[(size_t)br * N + col0 + bc4]);

    float acc[8][4];
#pragma unroll
    for (int i = 0; i < 8; i++)
#pragma unroll
        for (int j = 0; j < 4; j++) acc[i][j] = 0.f;

    int buf = 0;
    for (int k0 = 0; k0 < K; k0 += GBK) {
        float* as = buf ? As1 : As0;
        float* bs = buf ? Bs1 : Bs0;
        // store staged regs (A transposed)
        as[(ac4 + 0) * AP + ar0] = aR0.x;
        as[(ac4 + 1) * AP + ar0] = aR0.y;
        as[(ac4 + 2) * AP + ar0] = aR0.z;
        as[(ac4 + 3) * AP + ar0] = aR0.w;
        as[(ac4 + 0) * AP + ar0 + 64] = aR1.x;
        as[(ac4 + 1) * AP + ar0 + 64] = aR1.y;
        as[(ac4 + 2) * AP + ar0 + 64] = aR1.z;
        as[(ac4 + 3) * AP + ar0 + 64] = aR1.w;
        *reinterpret_cast<float4*>(&bs[br * BP + bc4]) = bR;
        __syncthreads();

        if (k0 + GBK < K) {
            aR0 = *reinterpret_cast<const float4*>(&A[(size_t)(row0 + ar0) * K + k0 + GBK + ac4]);
            aR1 = *reinterpret_cast<const float4*>(&A[(size_t)(row0 + ar0 + 64) * K + k0 + GBK + ac4]);
            bR  = *reinterpret_cast<const float4*>(&B[(size_t)(k0 + GBK + br) * N + col0 + bc4]);
        }

#pragma unroll
        for (int kk = 0; kk < GBK; kk++) {
            float4 a0 = *reinterpret_cast<float4*>(&as[kk * AP + ty * 8]);
            float4 a1 = *reinterpret_cast<float4*>(&as[kk * AP + ty * 8 + 4]);
            float4 b4 = *reinterpret_cast<float4*>(&bs[kk * BP + tx * 4]);
            float a[8] = {a0.x, a0.y, a0.z, a0.w, a1.x, a1.y, a1.z, a1.w};
            float b[4] = {b4.x, b4.y, b4.z, b4.w};
#pragma unroll
            for (int i = 0; i < 8; i++)
#pragma unroll
                for (int j = 0; j < 4; j++) acc[i][j] += a[i] * b[j];
        }
        buf ^= 1;
    }

    float4 bv = *reinterpret_cast<const float4*>(&bias[col0 + tx * 4]);
#pragma unroll
    for (int i = 0; i < 8; i++) {
        float4 r;
        r.x = acc[i][0] + bv.x;
        r.y = acc[i][1] + bv.y;
        r.z = acc[i][2] + bv.z;
        r.w = acc[i][3] + bv.w;
        *reinterpret_cast<float4*>(&C[(size_t)(row0 + ty * 8 + i) * N + col0 + tx * 4]) = r;
    }
}

// Fused Q-proj + KV-proj in one launch (768 blocks total)
__global__ __launch_bounds__(256) void proj_dual(
    const float* __restrict__ query, const float* __restrict__ value,
    const float* __restrict__ wq, const float* __restrict__ wqb,
    const float* __restrict__ wkv, const float* __restrict__ wkvb,
    float* __restrict__ outq, float* __restrict__ outkv)
{
    __shared__ float sm[SG_SMEM];
    const int bx = blockIdx.x, by = blockIdx.y;
    if (bx < 8)
        sgemm_body(query, wq, wqb, outq, D_MODEL, D_MODEL, by * GBM, bx * GBN, sm);
    else
        sgemm_body(value, wkv, wkvb, outkv, KV_W, D_MODEL, by * GBM, (bx - 8) * GBN, sm);
}

__global__ __launch_bounds__(256) void sgemm2(
    const float* __restrict__ A, const float* __restrict__ B,
    const float* __restrict__ bias, float* __restrict__ C, int N, int K)
{
    __shared__ float sm[SG_SMEM];
    sgemm_body(A, B, bias, C, N, K, blockIdx.y * GBM, blockIdx.x * GBN, sm);
}

// ---------------- causal flash attention v2 ----------------
// BM=128 queries, BN=128 keys per tile, 256 threads.
// QK: s[8][8] frags (ty: 16x8 queries, tx: 16x8 keys) -> 4 FMA per loaded float.
// PV: o[8][4] frags (ty: queries, tx: 16x4 head dims).
// Smem: Qt/Kt dim-major (pitch 132), Vs key-major (pitch 68), Ps [query][key] (pitch 132).
#define QT_OFF 0
#define KT_OFF 8448
#define VS_OFF 16896
#define PS_OFF 25600
#define FA_SMEM_FLOATS 42496      // 169984 bytes

__global__ __launch_bounds__(256, 1) void flash_attn2(
    const float* __restrict__ Q, const float* __restrict__ KV,
    float* __restrict__ O)
{
    extern __shared__ float sm[];
    float* Qt = sm + QT_OFF;   // [64][132]  dim-major queries
    float* Kt = sm + KT_OFF;   // [64][132]  dim-major keys
    float* Vs = sm + VS_OFF;   // [128][68]  key-major values
    float* Ps = sm + PS_OFF;   // [128][132] [query][key]

    const int qb = gridDim.x - 1 - blockIdx.x;   // heavy first
    const int h  = blockIdx.y;
    const int tid = threadIdx.x;
    const int tx = tid & 15;
    const int ty = tid >> 4;
    const int q0 = qb * 128;

    // load Q transposed + prescaled (1/sqrt(64))
    for (int e = tid; e < 128 * 16; e += 256) {
        const int r = e >> 4, c4 = (e & 15) * 4;
        float4 v = *reinterpret_cast<const float4*>(&Q[(size_t)(q0 + r) * D_MODEL + h * HD + c4]);
        Qt[(c4 + 0) * 132 + r] = v.x * 0.125f;
        Qt[(c4 + 1) * 132 + r] = v.y * 0.125f;
        Qt[(c4 + 2) * 132 + r] = v.z * 0.125f;
        Qt[(c4 + 3) * 132 + r] = v.w * 0.125f;
    }

    float o[8][4];
    float m_i[8], l_i[8];
#pragma unroll
    for (int i = 0; i < 8; i++) {
        m_i[i] = -1e30f; l_i[i] = 0.f;
#pragma unroll
        for (int j = 0; j < 4; j++) o[i][j] = 0.f;
    }

    for (int kb = 0; kb <= qb; kb++) {
        const int k0 = kb * 128;

        __syncthreads();   // prior Ps/Vs reads done; Qt ready on iter 0
        // K tile, transposed to dim-major
        for (int e = tid; e < 128 * 16; e += 256) {
            const int r = e >> 4, c4 = (e & 15) * 4;
            float4 v = *reinterpret_cast<const float4*>(&KV[(size_t)(k0 + r) * KV_W + h * HD + c4]);
            Kt[(c4 + 0) * 132 + r] = v.x;
            Kt[(c4 + 1) * 132 + r] = v.y;
            Kt[(c4 + 2) * 132 + r] = v.z;
            Kt[(c4 + 3) * 132 + r] = v.w;
        }
        // V tile, key-major
        for (int e = tid; e < 128 * 16; e += 256) {
            const int r = e >> 4, c4 = (e & 15) * 4;
            float4 v = *reinterpret_cast<const float4*>(&KV[(size_t)(k0 + r) * KV_W + D_MODEL + h * HD + c4]);
            *reinterpret_cast<float4*>(&Vs[r * 68 + c4]) = v;
        }
        __syncthreads();

        // S = Q K^T, 8x8 fragment
        float s[8][8];
#pragma unroll
        for (int i = 0; i < 8; i++)
#pragma unroll
            for (int j = 0; j < 8; j++) s[i][j] = 0.f;

#pragma unroll 8
        for (int kk = 0; kk < 64; kk++) {
            float4 a0 = *reinterpret_cast<float4*>(&Qt[kk * 132 + ty * 8]);
            float4 a1 = *reinterpret_cast<float4*>(&Qt[kk * 132 + ty * 8 + 4]);
            float4 b0 = *reinterpret_cast<float4*>(&Kt[kk * 132 + tx * 8]);
            float4 b1 = *reinterpret_cast<float4*>(&Kt[kk * 132 + tx * 8 + 4]);
            float a[8] = {a0.x, a0.y, a0.z, a0.w, a1.x, a1.y, a1.z, a1.w};
            float b[8] = {b0.x, b0.y, b0.z, b0.w, b1.x, b1.y, b1.z, b1.w};
#pragma unroll
            for (int i = 0; i < 8; i++)
#pragma unroll
                for (int j = 0; j < 8; j++) s[i][j] += a[i] * b[j];
        }

        if (kb == qb) {
#pragma unroll
            for (int i = 0; i < 8; i++)
#pragma unroll
                for (int j = 0; j < 8; j++)
                    if (tx * 8 + j > ty * 8 + i) s[i][j] = -1e30f;
        }

        // online softmax, rows owned by ty, reduce across 16 tx lanes
#pragma unroll
        for (int i = 0; i < 8; i++) {
            float mx = s[i][0];
#pragma unroll
            for (int j = 1; j < 8; j++) mx = fmaxf(mx, s[i][j]);
#pragma unroll
            for (int off = 8; off >= 1; off >>= 1)
                mx = fmaxf(mx, __shfl_xor_sync(0xffffffffu, mx, off, 16));

            const float m_new = fmaxf(m_i[i], mx);
            const float alpha = __expf(m_i[i] - m_new);
            float rs = 0.f;
#pragma unroll
            for (int j = 0; j < 8; j++) {
                s[i][j] = __expf(s[i][j] - m_new);
                rs += s[i][j];
            }
#pragma unroll
            for (int off = 8; off >= 1; off >>= 1)
                rs += __shfl_xor_sync(0xffffffffu, rs, off, 16);

            l_i[i] = l_i[i] * alpha + rs;
            m_i[i] = m_new;
#pragma unroll
            for (int j = 0; j < 4; j++) o[i][j] *= alpha;

            float4 p0 = make_float4(s[i][0], s[i][1], s[i][2], s[i][3]);
            float4 p1 = make_float4(s[i][4], s[i][5], s[i][6], s[i][7]);
            *reinterpret_cast<float4*>(&Ps[(ty * 8 + i) * 132 + tx * 8]) = p0;
            *reinterpret_cast<float4*>(&Ps[(ty * 8 + i) * 132 + tx * 8 + 4]) = p1;
        }
        __syncthreads();

        // O += P V  (p-loads broadcast; v-load vectorized)
#pragma unroll 4
        for (int kk = 0; kk < 128; kk++) {
            float4 v4 = *reinterpret_cast<float4*>(&Vs[kk * 68 + tx * 4]);
#pragma unroll
            for (int i = 0; i < 8; i++) {
                const float p = Ps[(ty * 8 + i) * 132 + kk];
                o[i][0] += p * v4.x;
                o[i][1] += p * v4.y;
                o[i][2] += p * v4.z;
                o[i][3] += p * v4.w;
            }
        }
    }

    // normalize + write
#pragma unroll
    for (int i = 0; i < 8; i++) {
        const float inv = 1.f / l_i[i];
        float4 r = make_float4(o[i][0] * inv, o[i][1] * inv, o[i][2] * inv, o[i][3] * inv);
        *reinterpret_cast<float4*>(&O[(size_t)(q0 + ty * 8 + i) * D_MODEL + h * HD + tx * 4]) = r;
    }
}

// ---------------- launch ----------------
extern "C" void kernel_launch(void* const* d_in, const int* in_sizes, int n_in,
                              void* d_out, int out_size)
{
    const float* query = (const float*)d_in[0];
    const float* value = (const float*)d_in[1];
    // d_in[2]: additive causal mask -> handled structurally
    const float* wq_k  = (const float*)d_in[3];
    const float* wq_b  = (const float*)d_in[4];
    const float* wkv_k = (const float*)d_in[5];
    const float* wkv_b = (const float*)d_in[6];
    const float* wo_k  = (const float*)d_in[7];
    const float* wo_b  = (const float*)d_in[8];
    float* out = (float*)d_out;

    float *q_ptr = nullptr, *kv_ptr = nullptr, *att_ptr = nullptr;
    cudaGetSymbolAddress((void**)&q_ptr,  g_q);
    cudaGetSymbolAddress((void**)&kv_ptr, g_kv);
    cudaGetSymbolAddress((void**)&att_ptr, g_att);

    // fused Q + KV projections: 768 blocks
    proj_dual<<<dim3(8 + 16, S_LEN / GBM), 256>>>(
        query, value, wq_k, wq_b, wkv_k, wkv_b, q_ptr, kv_ptr);

    // causal flash attention
    const int fa_smem = FA_SMEM_FLOATS * (int)sizeof(float);
    cudaFuncSetAttribute(flash_attn2, cudaFuncAttributeMaxDynamicSharedMemorySize, fa_smem);
    flash_attn2<<<dim3(S_LEN / 128, N_HEADS), 256, fa_smem>>>(q_ptr, kv_ptr, att_ptr);

    // output projection
    sgemm2<<<dim3(D_MODEL / GBN, S_LEN / GBM), 256>>>(
        att_ptr, wo_k, wo_b, out, D_MODEL, D_MODEL);
}

// round 3
// speedup vs baseline: 2.5891x; 2.4288x over previous
#include <cuda_runtime.h>
#include <cstdint>

#define S_LEN 4096
#define D_MODEL 512
#define KV_W 1024
#define N_HEADS 8

// ---------------- scratch ----------------
__device__ float g_q[S_LEN * D_MODEL];
__device__ float g_kv[S_LEN * KV_W];
__device__ float g_att[S_LEN * D_MODEL];

// ---------------- tf32 helpers ----------------
__device__ __forceinline__ float cvt_tf32(float x) {
    uint32_t u;
    asm("cvt.rna.tf32.f32 %0, %1;" : "=r"(u) : "f"(x));
    return __uint_as_float(u);
}

// D += A(16x8,row) * B(8x8,col), tf32 in, f32 accum
__device__ __forceinline__ void mma_tf32(float* d, const uint32_t* a, const uint32_t* b) {
    asm volatile(
        "mma.sync.aligned.m16n8k8.row.col.f32.tf32.tf32.f32 "
        "{%0,%1,%2,%3}, {%4,%5,%6,%7}, {%8,%9}, {%0,%1,%2,%3};"
        : "+f"(d[0]), "+f"(d[1]), "+f"(d[2]), "+f"(d[3])
        : "r"(a[0]), "r"(a[1]), "r"(a[2]), "r"(a[3]), "r"(b[0]), "r"(b[1]));
}

// ---------------- tf32 GEMM: C[M,N] = A[M,512] @ B[512,N] + bias ----------------
// BM=128 BN=128 BK=16, 256 threads (8 warps: 4m x 2n), warp tile 32x64.
#define GBK 16
#define GAP 20     // As pitch [m][k]: banks (20g+t)%32 distinct
#define GBP 136    // Bs pitch [k][n]: banks (136t+g)%32 = 8t+g distinct
#define G_SMEM (2 * (128 * GAP + GBK * GBP))   // 9472 floats

__device__ __forceinline__ void gemm_body(
    const float* __restrict__ A, const float* __restrict__ B,
    const float* __restrict__ bias, float* __restrict__ C,
    int N, int row0, int col0, float* sm)
{
    float* As0 = sm;
    float* As1 = As0 + 128 * GAP;
    float* Bs0 = As1 + 128 * GAP;
    float* Bs1 = Bs0 + GBK * GBP;

    const int tid = threadIdx.x;
    const int lane = tid & 31;
    const int warp = tid >> 5;
    const int wm = (warp & 3) * 32;
    const int wn = (warp >> 2) * 64;
    const int g = lane >> 2, t = lane & 3;

    // staging: A rows of 16 floats (2 threads/row, 8 floats each);
    //          B rows of 128 floats (16 threads/row, 8 floats each)
    const int arow = tid >> 1, acol = (tid & 1) * 8;
    const int brow = tid >> 4, bcol = (tid & 15) * 8;

    const float* Ap = A + (size_t)(row0 + arow) * D_MODEL + acol;
    const float* Bp = B + (size_t)brow * N + col0 + bcol;

    float4 pa0 = *(const float4*)(Ap);
    float4 pa1 = *(const float4*)(Ap + 4);
    float4 pb0 = *(const float4*)(Bp);
    float4 pb1 = *(const float4*)(Bp + 4);

    float acc[2][8][4];
#pragma unroll
    for (int mt = 0; mt < 2; mt++)
#pragma unroll
        for (int nt = 0; nt < 8; nt++)
#pragma unroll
            for (int c = 0; c < 4; c++) acc[mt][nt][c] = 0.f;

    // store iter-0 tiles
    {
        float* as = As0; float* bs = Bs0;
        as[arow * GAP + acol + 0] = cvt_tf32(pa0.x);
        as[arow * GAP + acol + 1] = cvt_tf32(pa0.y);
        as[arow * GAP + acol + 2] = cvt_tf32(pa0.z);
        as[arow * GAP + acol + 3] = cvt_tf32(pa0.w);
        as[arow * GAP + acol + 4] = cvt_tf32(pa1.x);
        as[arow * GAP + acol + 5] = cvt_tf32(pa1.y);
        as[arow * GAP + acol + 6] = cvt_tf32(pa1.z);
        as[arow * GAP + acol + 7] = cvt_tf32(pa1.w);
        bs[brow * GBP + bcol + 0] = cvt_tf32(pb0.x);
        bs[brow * GBP + bcol + 1] = cvt_tf32(pb0.y);
        bs[brow * GBP + bcol + 2] = cvt_tf32(pb0.z);
        bs[brow * GBP + bcol + 3] = cvt_tf32(pb0.w);
        bs[brow * GBP + bcol + 4] = cvt_tf32(pb1.x);
        bs[brow * GBP + bcol + 5] = cvt_tf32(pb1.y);
        bs[brow * GBP + bcol + 6] = cvt_tf32(pb1.z);
        bs[brow * GBP + bcol + 7] = cvt_tf32(pb1.w);
    }
    __syncthreads();

    for (int it = 0; it < 32; it++) {
        const uint32_t* asu = (const uint32_t*)((it & 1) ? As1 : As0);
        const uint32_t* bsu = (const uint32_t*)((it & 1) ? Bs1 : Bs0);

        if (it < 31) {   // prefetch next tiles to regs
            const float* ap = Ap + (it + 1) * GBK;
            const float* bp = Bp + (size_t)(it + 1) * GBK * N;
            pa0 = *(const float4*)(ap);
            pa1 = *(const float4*)(ap + 4);
            pb0 = *(const float4*)(bp);
            pb1 = *(const float4*)(bp + 4);
        }

#pragma unroll
        for (int ks = 0; ks < 2; ks++) {
            uint32_t a[2][4], b[8][2];
#pragma unroll
            for (int mt = 0; mt < 2; mt++) {
                const int r = wm + mt * 16 + g;
                a[mt][0] = asu[r * GAP + ks * 8 + t];
                a[mt][1] = asu[(r + 8) * GAP + ks * 8 + t];
                a[mt][2] = asu[r * GAP + ks * 8 + t + 4];
                a[mt][3] = asu[(r + 8) * GAP + ks * 8 + t + 4];
            }
#pragma unroll
            for (int nt = 0; nt < 8; nt++) {
                b[nt][0] = bsu[(ks * 8 + t) * GBP + wn + nt * 8 + g];
                b[nt][1] = bsu[(ks * 8 + t + 4) * GBP + wn + nt * 8 + g];
            }
#pragma unroll
            for (int mt = 0; mt < 2; mt++)
#pragma unroll
                for (int nt = 0; nt < 8; nt++)
                    mma_tf32(acc[mt][nt], a[mt], b[nt]);
        }

        if (it < 31) {
            float* as = (it & 1) ? As0 : As1;
            float* bs = (it & 1) ? Bs0 : Bs1;
            as[arow * GAP + acol + 0] = cvt_tf32(pa0.x);
            as[arow * GAP + acol + 1] = cvt_tf32(pa0.y);
            as[arow * GAP + acol + 2] = cvt_tf32(pa0.z);
            as[arow * GAP + acol + 3] = cvt_tf32(pa0.w);
            as[arow * GAP + acol + 4] = cvt_tf32(pa1.x);
            as[arow * GAP + acol + 5] = cvt_tf32(pa1.y);
            as[arow * GAP + acol + 6] = cvt_tf32(pa1.z);
            as[arow * GAP + acol + 7] = cvt_tf32(pa1.w);
            bs[brow * GBP + bcol + 0] = cvt_tf32(pb0.x);
            bs[brow * GBP + bcol + 1] = cvt_tf32(pb0.y);
            bs[brow * GBP + bcol + 2] = cvt_tf32(pb0.z);
            bs[brow * GBP + bcol + 3] = cvt_tf32(pb0.w);
            bs[brow * GBP + bcol + 4] = cvt_tf32(pb1.x);
            bs[brow * GBP + bcol + 5] = cvt_tf32(pb1.y);
            bs[brow * GBP + bcol + 6] = cvt_tf32(pb1.z);
            bs[brow * GBP + bcol + 7] = cvt_tf32(pb1.w);
            __syncthreads();
        }
    }

    // epilogue: bias + store (c0,c1) rows g / (c2,c3) rows g+8
#pragma unroll
    for (int mt = 0; mt < 2; mt++) {
        const int r = row0 + wm + mt * 16 + g;
#pragma unroll
        for (int nt = 0; nt < 8; nt++) {
            const int c = col0 + wn + nt * 8 + 2 * t;
            const float2 bv = *(const float2*)(bias + c);
            float2 v0 = make_float2(acc[mt][nt][0] + bv.x, acc[mt][nt][1] + bv.y);
            float2 v1 = make_float2(acc[mt][nt][2] + bv.x, acc[mt][nt][3] + bv.y);
            *(float2*)(C + (size_t)r * N + c) = v0;
            *(float2*)(C + (size_t)(r + 8) * N + c) = v1;
        }
    }
}

__global__ __launch_bounds__(256) void proj_dual(
    const float* __restrict__ query, const float* __restrict__ value,
    const float* __restrict__ wq, const float* __restrict__ wqb,
    const float* __restrict__ wkv, const float* __restrict__ wkvb,
    float* __restrict__ outq, float* __restrict__ outkv)
{
    __shared__ float sm[G_SMEM];
    const int bx = blockIdx.x, by = blockIdx.y;
    if (bx < 4)
        gemm_body(query, wq, wqb, outq, D_MODEL, by * 128, bx * 128, sm);
    else
        gemm_body(value, wkv, wkvb, outkv, KV_W, by * 128, (bx - 4) * 128, sm);
}

__global__ __launch_bounds__(256) void out_proj(
    const float* __restrict__ A, const float* __restrict__ B,
    const float* __restrict__ bias, float* __restrict__ C)
{
    __shared__ float sm[G_SMEM];
    gemm_body(A, B, bias, C, D_MODEL, blockIdx.y * 128, blockIdx.x * 128, sm);
}

// ---------------- causal flash attention on mma.sync tf32 ----------------
// 128 threads = 4 warps; CTA tile 128 q x 64 keys; warp tile 32 q x 64 keys.
#define AQ_P 68   // Qs pitch [q][hd]   : a-frag banks 4g+t
#define AK_P 68   // Ks pitch [key][hd] : QK b-frag banks 4g+t
#define AV_P 72   // Vs pitch [key][hd] : PV b-frag banks 8t+g
#define APP 68    // Ps pitch [q][key]  : a-frag banks 4g+t
#define FA_SMEM_FLOATS (128 * AQ_P + 64 * AK_P + 64 * AV_P + 128 * APP)  // 26368

__global__ __launch_bounds__(128) void flash_attn_mma(
    const float* __restrict__ Q, const float* __restrict__ KV,
    float* __restrict__ O)
{
    extern __shared__ float sm[];
    float* Qs = sm;
    float* Ks = Qs + 128 * AQ_P;
    float* Vs = Ks + 64 * AK_P;
    float* Ps = Vs + 64 * AV_P;

    const int qb = gridDim.x - 1 - blockIdx.x;    // heavy first
    const int h  = blockIdx.y;
    const int tid = threadIdx.x;
    const int lane = tid & 31, warp = tid >> 5;
    const int g = lane >> 2, t = lane & 3;
    const int q0 = qb * 128;

    // stage Q tile, prescaled by 1/sqrt(64)=0.125, rounded to tf32
#pragma unroll
    for (int i = 0; i < 16; i++) {
        const int e = tid + 128 * i;
        const int r = e >> 4, c4 = (e & 15) * 4;
        float4 v = *(const float4*)(Q + (size_t)(q0 + r) * D_MODEL + h * 64 + c4);
        Qs[r * AQ_P + c4 + 0] = cvt_tf32(v.x * 0.125f);
        Qs[r * AQ_P + c4 + 1] = cvt_tf32(v.y * 0.125f);
        Qs[r * AQ_P + c4 + 2] = cvt_tf32(v.z * 0.125f);
        Qs[r * AQ_P + c4 + 3] = cvt_tf32(v.w * 0.125f);
    }

    float o[2][8][4];
    float m_i[4], l_i[4];
#pragma unroll
    for (int i = 0; i < 4; i++) { m_i[i] = -1e30f; l_i[i] = 0.f; }
#pragma unroll
    for (int mt = 0; mt < 2; mt++)
#pragma unroll
        for (int nt = 0; nt < 8; nt++)
#pragma unroll
            for (int c = 0; c < 4; c++) o[mt][nt][c] = 0.f;

    const int ntiles = 2 * qb + 2;
    for (int kb = 0; kb < ntiles; kb++) {
        const int k0 = kb * 64;

        __syncthreads();   // prior tile's K/V reads complete
#pragma unroll
        for (int i = 0; i < 8; i++) {
            const int e = tid + 128 * i;
            const int r = e >> 4, c4 = (e & 15) * 4;
            float4 kv4 = *(const float4*)(KV + (size_t)(k0 + r) * KV_W + h * 64 + c4);
            Ks[r * AK_P + c4 + 0] = cvt_tf32(kv4.x);
            Ks[r * AK_P + c4 + 1] = cvt_tf32(kv4.y);
            Ks[r * AK_P + c4 + 2] = cvt_tf32(kv4.z);
            Ks[r * AK_P + c4 + 3] = cvt_tf32(kv4.w);
            float4 vv = *(const float4*)(KV + (size_t)(k0 + r) * KV_W + D_MODEL + h * 64 + c4);
            Vs[r * AV_P + c4 + 0] = cvt_tf32(vv.x);
            Vs[r * AV_P + c4 + 1] = cvt_tf32(vv.y);
            Vs[r * AV_P + c4 + 2] = cvt_tf32(vv.z);
            Vs[r * AV_P + c4 + 3] = cvt_tf32(vv.w);
        }
        __syncthreads();

        // ---- S = Q K^T ----
        float s[2][8][4];
#pragma unroll
        for (int mt = 0; mt < 2; mt++)
#pragma unroll
            for (int nt = 0; nt < 8; nt++)
#pragma unroll
                for (int c = 0; c < 4; c++) s[mt][nt][c] = 0.f;

        const uint32_t* Qu = (const uint32_t*)Qs;
        const uint32_t* Ku = (const uint32_t*)Ks;
#pragma unroll
        for (int ks = 0; ks < 8; ks++) {
            uint32_t a[2][4];
#pragma unroll
            for (int mt = 0; mt < 2; mt++) {
                const int r = warp * 32 + mt * 16 + g;
                a[mt][0] = Qu[r * AQ_P + ks * 8 + t];
                a[mt][1] = Qu[(r + 8) * AQ_P + ks * 8 + t];
                a[mt][2] = Qu[r * AQ_P + ks * 8 + t + 4];
                a[mt][3] = Qu[(r + 8) * AQ_P + ks * 8 + t + 4];
            }
#pragma unroll
            for (int nt = 0; nt < 8; nt++) {
                uint32_t b[2];
                b[0] = Ku[(nt * 8 + g) * AK_P + ks * 8 + t];
                b[1] = Ku[(nt * 8 + g) * AK_P + ks * 8 + t + 4];
                mma_tf32(s[0][nt], a[0], b);
                mma_tf32(s[1][nt], a[1], b);
            }
        }

        // causal mask (only the two diagonal-region tiles)
        if (kb >= 2 * qb) {
#pragma unroll
            for (int mt = 0; mt < 2; mt++)
#pragma unroll
                for (int nt = 0; nt < 8; nt++)
#pragma unroll
                    for (int c = 0; c < 4; c++) {
                        const int row = warp * 32 + mt * 16 + g + (c >> 1) * 8;
                        const int col = k0 + nt * 8 + 2 * t + (c & 1);
                        if (col > q0 + row) s[mt][nt][c] = -1e30f;
                    }
        }

        // ---- online softmax (4 owned rows per thread) ----
#pragma unroll
        for (int mt = 0; mt < 2; mt++) {
#pragma unroll
            for (int sr = 0; sr < 2; sr++) {
                const int idx = mt * 2 + sr;
                float mx = -1e30f;
#pragma unroll
                for (int nt = 0; nt < 8; nt++)
                    mx = fmaxf(mx, fmaxf(s[mt][nt][2 * sr], s[mt][nt][2 * sr + 1]));
                mx = fmaxf(mx, __shfl_xor_sync(0xffffffffu, mx, 1, 4));
                mx = fmaxf(mx, __shfl_xor_sync(0xffffffffu, mx, 2, 4));

                const float m_new = fmaxf(m_i[idx], mx);
                const float alpha = __expf(m_i[idx] - m_new);
                float rs = 0.f;
#pragma unroll
                for (int nt = 0; nt < 8; nt++) {
                    const float p0 = __expf(s[mt][nt][2 * sr] - m_new);
                    const float p1 = __expf(s[mt][nt][2 * sr + 1] - m_new);
                    s[mt][nt][2 * sr] = p0;
                    s[mt][nt][2 * sr + 1] = p1;
                    rs += p0 + p1;
                }
                rs += __shfl_xor_sync(0xffffffffu, rs, 1, 4);
                rs += __shfl_xor_sync(0xffffffffu, rs, 2, 4);

                l_i[idx] = l_i[idx] * alpha + rs;
                m_i[idx] = m_new;
#pragma unroll
                for (int nt = 0; nt < 8; nt++) {
                    o[mt][nt][2 * sr] *= alpha;
                    o[mt][nt][2 * sr + 1] *= alpha;
                }
                const int r = warp * 32 + mt * 16 + g + 8 * sr;
#pragma unroll
                for (int nt = 0; nt < 8; nt++) {
                    float2 pv = make_float2(cvt_tf32(s[mt][nt][2 * sr]),
                                            cvt_tf32(s[mt][nt][2 * sr + 1]));
                    *(float2*)(Ps + r * APP + nt * 8 + 2 * t) = pv;
                }
            }
        }
        __syncwarp();   // Ps is warp-private: warp-level ordering suffices

        // ---- O += P V ----
        const uint32_t* Pu = (const uint32_t*)Ps;
        const uint32_t* Vu = (const uint32_t*)Vs;
#pragma unroll
        for (int ks = 0; ks < 8; ks++) {
            uint32_t a[2][4];
#pragma unroll
            for (int mt = 0; mt < 2; mt++) {
                const int r = warp * 32 + mt * 16 + g;
                a[mt][0] = Pu[r * APP + ks * 8 + t];
                a[mt][1] = Pu[(r + 8) * APP + ks * 8 + t];
                a[mt][2] = Pu[r * APP + ks * 8 + t + 4];
                a[mt][3] = Pu[(r + 8) * APP + ks * 8 + t + 4];
            }
#pragma unroll
            for (int nt = 0; nt < 8; nt++) {
                uint32_t b[2];
                b[0] = Vu[(ks * 8 + t) * AV_P + nt * 8 + g];
                b[1] = Vu[(ks * 8 + t + 4) * AV_P + nt * 8 + g];
                mma_tf32(o[0][nt], a[0], b);
                mma_tf32(o[1][nt], a[1], b);
            }
        }
    }

    // normalize + store
#pragma unroll
    for (int mt = 0; mt < 2; mt++) {
#pragma unroll
        for (int sr = 0; sr < 2; sr++) {
            const float inv = 1.f / l_i[mt * 2 + sr];
            const int r = q0 + warp * 32 + mt * 16 + g + 8 * sr;
#pragma unroll
            for (int nt = 0; nt < 8; nt++) {
                float2 w = make_float2(o[mt][nt][2 * sr] * inv,
                                       o[mt][nt][2 * sr + 1] * inv);
                *(float2*)(O + (size_t)r * D_MODEL + h * 64 + nt * 8 + 2 * t) = w;
            }
        }
    }
}

// ---------------- launch ----------------
extern "C" void kernel_launch(void* const* d_in, const int* in_sizes, int n_in,
                              void* d_out, int out_size)
{
    const float* query = (const float*)d_in[0];
    const float* value = (const float*)d_in[1];
    // d_in[2]: additive causal mask -> handled structurally
    const float* wq_k  = (const float*)d_in[3];
    const float* wq_b  = (const float*)d_in[4];
    const float* wkv_k = (const float*)d_in[5];
    const float* wkv_b = (const float*)d_in[6];
    const float* wo_k  = (const float*)d_in[7];
    const float* wo_b  = (const float*)d_in[8];
    float* out = (float*)d_out;

    float *q_ptr = nullptr, *kv_ptr = nullptr, *att_ptr = nullptr;
    cudaGetSymbolAddress((void**)&q_ptr,  g_q);
    cudaGetSymbolAddress((void**)&kv_ptr, g_kv);
    cudaGetSymbolAddress((void**)&att_ptr, g_att);

    // fused Q + KV projections (12x32 = 384 blocks)
    proj_dual<<<dim3(12, 32), 256>>>(query, value, wq_k, wq_b, wkv_k, wkv_b,
                                     q_ptr, kv_ptr);

    // causal flash attention on tensor cores
    const int fa_smem = FA_SMEM_FLOATS * (int)sizeof(float);   // 105472 B
    cudaFuncSetAttribute(flash_attn_mma, cudaFuncAttributeMaxDynamicSharedMemorySize, fa_smem);
    flash_attn_mma<<<dim3(S_LEN / 128, N_HEADS), 128, fa_smem>>>(q_ptr, kv_ptr, att_ptr);

    // output projection (4x32 = 128 blocks)
    out_proj<<<dim3(4, 32), 256>>>(att_ptr, wo_k, wo_b, out);
}